// round 15
// baseline (speedup 1.0000x reference)
#include <cuda_runtime.h>
#include <cuda_fp16.h>
#include <cstdint>
#include <math.h>

typedef __half h16;

// Problem constants
#define Bb   2
#define Ss   2048
#define Dd   512
#define Hh   8
#define DHh  64
#define DHID 1024
#define NBLK 12
#define MTOT (Bb * Ss)      // 4096 rows
// 1/sqrt(512) * log2(e): logits emerge in log2 domain -> bare ex2 in softmax
#define QSCALE 0.06375871648f

#define FLAG_RES  1
#define FLAG_RELU 2
#define FLAG_OUTH 8

// ---------------------------------------------------------------------------
// Scratch (device globals) — fp32 residual stream, fp16 operands
// ---------------------------------------------------------------------------
__device__ float g_x  [MTOT * Dd];           // fp32 residual state
__device__ h16   g_qkvb[MTOT * 3 * Dd];      // fp16 qkv (q pre-scaled by QSCALE)
__device__ float g_qkvbias[NBLK * 3 * Dd];   // scaled qkv bias

__device__ h16 g_X16 [MTOT * Dd];
__device__ h16 g_x16 [MTOT * Dd];
__device__ h16 g_xn16[MTOT * Dd];
__device__ h16 g_at16[MTOT * Dd];
__device__ h16 g_h116[MTOT * DHID];

// Transposed fp16 weights: [blk][N][K]
__device__ h16 g_qkvwT[NBLK * 1536 * 512];
__device__ h16 g_fcwT [NBLK * 512 * 512];
__device__ h16 g_w1T  [NBLK * 1024 * 512];
__device__ h16 g_w2T  [NBLK * 512 * 1024];

// ---------------------------------------------------------------------------
// PTX helpers
// ---------------------------------------------------------------------------
__device__ __forceinline__ uint32_t smem_u32(const void* p) {
    uint32_t a;
    asm("{ .reg .u64 t; cvta.to.shared.u64 t, %1; cvt.u32.u64 %0, t; }"
        : "=r"(a) : "l"(p));
    return a;
}
__device__ __forceinline__ void cpa16(uint32_t s, const void* g) {
    asm volatile("cp.async.ca.shared.global [%0], [%1], 16;" :: "r"(s), "l"(g));
}
__device__ __forceinline__ void cp_commit() {
    asm volatile("cp.async.commit_group;" ::: "memory");
}
__device__ __forceinline__ void cp_wait2() {
    asm volatile("cp.async.wait_group 2;" ::: "memory");
}
__device__ __forceinline__ void cp_wait1() {
    asm volatile("cp.async.wait_group 1;" ::: "memory");
}
__device__ __forceinline__ void cp_wait0() {
    asm volatile("cp.async.wait_group 0;" ::: "memory");
}
__device__ __forceinline__ void ldsm4(uint32_t a[4], uint32_t addr) {
    asm volatile("ldmatrix.sync.aligned.m8n8.x4.shared.b16 {%0,%1,%2,%3}, [%4];"
                 : "=r"(a[0]), "=r"(a[1]), "=r"(a[2]), "=r"(a[3]) : "r"(addr));
}
__device__ __forceinline__ void ldsm4t(uint32_t a[4], uint32_t addr) {
    asm volatile("ldmatrix.sync.aligned.m8n8.x4.trans.shared.b16 {%0,%1,%2,%3}, [%4];"
                 : "=r"(a[0]), "=r"(a[1]), "=r"(a[2]), "=r"(a[3]) : "r"(addr));
}
__device__ __forceinline__ void mma_f16(float c[4], const uint32_t a[4],
                                        const uint32_t b[2]) {
    asm volatile(
        "mma.sync.aligned.m16n8k16.row.col.f32.f16.f16.f32 "
        "{%0,%1,%2,%3}, {%4,%5,%6,%7}, {%8,%9}, {%0,%1,%2,%3};"
        : "+f"(c[0]), "+f"(c[1]), "+f"(c[2]), "+f"(c[3])
        : "r"(a[0]), "r"(a[1]), "r"(a[2]), "r"(a[3]), "r"(b[0]), "r"(b[1]));
}
__device__ __forceinline__ uint32_t packh(float lo, float hi) {
    uint32_t u;
    asm("cvt.rn.f16x2.f32 %0, %1, %2;" : "=r"(u) : "f"(hi), "f"(lo));
    return u;
}
// bare exp2 (logits pre-multiplied by log2e); clamp keeps fp16 P finite
__device__ __forceinline__ float fexp2(float x) {
    float y;
    asm("ex2.approx.f32 %0, %1;" : "=f"(y) : "f"(fminf(x, 14.f)));
    return y;
}

// ---------------------------------------------------------------------------
// Weight transpose to fp16: W[K,N] -> T[N,K], per blockIdx.z.
// qmode: scale q-part columns (n%192 < 64) by QSCALE (qkv only).
// ---------------------------------------------------------------------------
__global__ __launch_bounds__(256) void transpose_kernel(
    const float* __restrict__ W, h16* __restrict__ T, int K, int N, int qmode)
{
    __shared__ float ts[32][33];
    const int z = blockIdx.z;
    W += (size_t)z * K * N;
    T += (size_t)z * N * K;
    const int n0 = blockIdx.x * 32, k0 = blockIdx.y * 32;
    const int tx = threadIdx.x, ty = threadIdx.y;   // (32, 8)
#pragma unroll
    for (int i = 0; i < 4; i++)
        ts[ty + i * 8][tx] = W[(size_t)(k0 + ty + i * 8) * N + n0 + tx];
    __syncthreads();
#pragma unroll
    for (int i = 0; i < 4; i++) {
        int n = n0 + ty + i * 8;
        float v = ts[tx][ty + i * 8];
        if (qmode && (n % 192) < 64) v *= QSCALE;
        T[(size_t)n * K + k0 + tx] = __float2half_rn(v);
    }
}

// Merged transpose for fc/w1/w2, compact tile list (1280 tiles per blk):
//   [0,256): fc 16x16 tiles; [256,768): w1 32x16; [768,1280): w2 16x32
__global__ __launch_bounds__(256) void transpose3_kernel(
    const float* __restrict__ fc_w, const float* __restrict__ w1,
    const float* __restrict__ w2,
    h16* __restrict__ fcT, h16* __restrict__ w1T, h16* __restrict__ w2T)
{
    __shared__ float ts[32][33];
    const int blk = blockIdx.z;
    int id = blockIdx.x;
    const float* W; h16* T; int K, N, n0, k0;
    if (id < 256)      { W = fc_w; T = fcT; K = 512;  N = 512;
                         n0 = (id & 15) * 32;  k0 = (id >> 4) * 32; }
    else if (id < 768) { id -= 256; W = w1; T = w1T; K = 512;  N = 1024;
                         n0 = (id & 31) * 32;  k0 = (id >> 5) * 32; }
    else               { id -= 768; W = w2; T = w2T; K = 1024; N = 512;
                         n0 = (id & 15) * 32;  k0 = (id >> 4) * 32; }
    W += (size_t)blk * K * N;
    T += (size_t)blk * N * K;
    const int tx = threadIdx.x, ty = threadIdx.y;   // (32, 8)
#pragma unroll
    for (int i = 0; i < 4; i++)
        ts[ty + i * 8][tx] = W[(size_t)(k0 + ty + i * 8) * N + n0 + tx];
    __syncthreads();
#pragma unroll
    for (int i = 0; i < 4; i++)
        T[(size_t)(n0 + ty + i * 8) * K + k0 + tx] =
            __float2half_rn(ts[tx][ty + i * 8]);
}

// fp32 -> fp16 (elementwise)
__global__ __launch_bounds__(256) void convert_h_kernel(
    const float* __restrict__ in, h16* __restrict__ h, int n)
{
    int i = (blockIdx.x * 256 + threadIdx.x) * 4;
    if (i >= n) return;
    float4 v = *(const float4*)(in + i);
    *(uint2*)(h + i) = make_uint2(packh(v.x, v.y), packh(v.z, v.w));
}

// qkv bias, q-part scaled
__global__ __launch_bounds__(256) void scale_bias_kernel(
    const float* __restrict__ in, float* __restrict__ out)
{
    int i = blockIdx.x * 256 + threadIdx.x;
    if (i >= NBLK * 1536) return;
    int n = i % 1536;
    out[i] = in[i] * (((n % 192) < 64) ? QSCALE : 1.0f);
}

// ---------------------------------------------------------------------------
// fp16 GEMM via mma.sync, templated M-tile (MT = 128 or 64).
// C[M,N] = A @ W^T + bias (+res fp32)(+relu). A fp16 [M][K]; B fp16 [N][K].
// CTA MT x 128, BK=32, 8 warps (2m x 4n), warp tile (MT/2) x 32.
// smem: 3 stages x {As[MT][40], Bs[128][40]} halves (pitch 80B)
// ---------------------------------------------------------------------------
template <int FLAGS, int MT>
__global__ __launch_bounds__(256, 2) void gemm_mma(
    const h16* __restrict__ A, const h16* __restrict__ B,
    const float* __restrict__ bias, const float* __restrict__ R,
    float* __restrict__ C, h16* __restrict__ Ch, int K, int N)
{
    constexpr int MI  = MT / 32;              // 16-row frags per warp
    constexpr int ASZ = MT * 80;              // A bytes per stage
    constexpr int SSZ = ASZ + 128 * 80;       // stage bytes

    extern __shared__ char smraw[];
    const uint32_t sb = smem_u32(smraw);
    const int t = threadIdx.x, lane = t & 31, wid = t >> 5;
    const int row0 = blockIdx.y * MT, col0 = blockIdx.x * 128;
    const int m0 = (wid >> 2) * (MT / 2), n0 = (wid & 3) * 32;
    const int NI = K >> 5;

    float acc[MI][4][4];
#pragma unroll
    for (int a = 0; a < MI; a++)
#pragma unroll
        for (int b = 0; b < 4; b++)
#pragma unroll
            for (int c = 0; c < 4; c++) acc[a][b][c] = 0.f;

#define ISSUE(i) do {                                                          \
    uint32_t bo = sb + (uint32_t)((i) % 3) * SSZ;                              \
    _Pragma("unroll")                                                          \
    for (int c_ = t; c_ < MT * 4; c_ += 256) {                                 \
        int row_ = c_ >> 2, q_ = c_ & 3;                                       \
        cpa16(bo + row_ * 80 + q_ * 16,                                        \
              A + (size_t)(row0 + row_) * K + (i) * 32 + q_ * 8);              \
    }                                                                          \
    _Pragma("unroll")                                                          \
    for (int c_ = t; c_ < 512; c_ += 256) {                                    \
        int row_ = c_ >> 2, q_ = c_ & 3;                                       \
        cpa16(bo + ASZ + row_ * 80 + q_ * 16,                                  \
              B + (size_t)(col0 + row_) * K + (i) * 32 + q_ * 8);              \
    }                                                                          \
    cp_commit(); } while (0)

    ISSUE(0);
    ISSUE(1);
    for (int i = 0; i < NI; i++) {
        if (i + 2 < NI) { ISSUE(i + 2); cp_wait2(); }
        else if (i + 1 < NI) cp_wait1();
        else cp_wait0();
        __syncthreads();
        const uint32_t bufb = sb + (uint32_t)(i % 3) * SSZ;
#pragma unroll
        for (int ks = 0; ks < 2; ks++) {
            const int kb = ks * 16;
            uint32_t ah[MI][4], bh[4][2];
#pragma unroll
            for (int mi = 0; mi < MI; mi++) {
                uint32_t ad = bufb + (uint32_t)(((m0 + mi * 16 + (lane & 15)) * 40
                                                + kb + (lane >> 4) * 8) * 2);
                ldsm4(ah[mi], ad);
            }
            {
                const int l8 = lane & 7, q = lane >> 3;
                uint32_t bd = bufb + ASZ + (uint32_t)(((n0 + (q >> 1) * 8 + l8) * 40
                                                      + kb + (q & 1) * 8) * 2);
                uint32_t tmp[4];
                ldsm4(tmp, bd);
                bh[0][0] = tmp[0]; bh[0][1] = tmp[1]; bh[1][0] = tmp[2]; bh[1][1] = tmp[3];
                ldsm4(tmp, bd + 16 * 80);
                bh[2][0] = tmp[0]; bh[2][1] = tmp[1]; bh[3][0] = tmp[2]; bh[3][1] = tmp[3];
            }
#pragma unroll
            for (int mi = 0; mi < MI; mi++)
#pragma unroll
                for (int ni = 0; ni < 4; ni++)
                    mma_f16(acc[mi][ni], ah[mi], bh[ni]);
        }
        __syncthreads();
    }
#undef ISSUE

    // Epilogue
    const int gid = lane >> 2, tig = lane & 3;
#pragma unroll
    for (int mi = 0; mi < MI; mi++) {
        const int ra = row0 + m0 + mi * 16 + gid;
#pragma unroll
        for (int ni = 0; ni < 4; ni++) {
            const int col = col0 + n0 + ni * 8 + tig * 2;
            float2 bv = *(const float2*)(bias + col);
            float x0 = acc[mi][ni][0] + bv.x, x1 = acc[mi][ni][1] + bv.y;
            float x2 = acc[mi][ni][2] + bv.x, x3 = acc[mi][ni][3] + bv.y;
            if (FLAGS & FLAG_RES) {
                float2 r0 = *(const float2*)(R + (size_t)ra * N + col);
                float2 r1 = *(const float2*)(R + (size_t)(ra + 8) * N + col);
                x0 += r0.x; x1 += r0.y; x2 += r1.x; x3 += r1.y;
            }
            if (FLAGS & FLAG_RELU) {
                x0 = fmaxf(x0, 0.f); x1 = fmaxf(x1, 0.f);
                x2 = fmaxf(x2, 0.f); x3 = fmaxf(x3, 0.f);
            }
            if (FLAGS & FLAG_OUTH) {
                *(uint32_t*)(Ch + (size_t)ra * N + col) = packh(x0, x1);
                *(uint32_t*)(Ch + (size_t)(ra + 8) * N + col) = packh(x2, x3);
            } else {
                *(float2*)(C + (size_t)ra * N + col) = make_float2(x0, x1);
                *(float2*)(C + (size_t)(ra + 8) * N + col) = make_float2(x2, x3);
            }
        }
    }
}

#define GEMM_SMEM_128 (3 * (128 * 80 + 128 * 80))   // 61440
#define GEMM_SMEM_64  (3 * (64 * 80 + 128 * 80))    // 46080

// ---------------------------------------------------------------------------
// Flash attention: fp16 mma, 4 warps (32 q rows each), double-buffered K/V,
// no-max softmax in log2 domain (bare ex2), single final l reduction.
// Grid (S/128, H, B), 128 threads, 3 CTAs/SM (smem 55.3KB x 3 = 166KB).
// ---------------------------------------------------------------------------
#define KVBUF 9216                               // 64*144 B
#define ATT2_SMEM (128 * 144 + 4 * KVBUF)        // 55296

__global__ __launch_bounds__(128, 3) void attn_v2(
    const h16* __restrict__ qkvb, h16* __restrict__ atth)
{
    extern __shared__ char smc[];
    const uint32_t sQ = smem_u32(smc);
    const uint32_t sK = sQ + 128 * 144;          // 2 buffers
    const uint32_t sV = sK + 2 * KVBUF;          // 2 buffers

    const int t = threadIdx.x, lane = t & 31, wid = t >> 5;
    const int gid = lane >> 2, tig = lane & 3;
    const int l8 = lane & 7, g8 = lane >> 3;
    const int q0 = blockIdx.x * 128, h = blockIdx.y, b = blockIdx.z;
    const int m0 = wid * 32;
    const h16* base = qkvb + (size_t)b * Ss * 1536 + h * 192;

    // Q prologue
#pragma unroll
    for (int i = 0; i < 8; i++) {
        int c = t + i * 128;
        int row = c >> 3, c8 = c & 7;
        cpa16(sQ + row * 144 + c8 * 16,
              base + (size_t)(q0 + row) * 1536 + c8 * 8);
    }
    cp_commit();

#define ISSUE_KV(kt) do {                                                     \
    uint32_t kb_ = sK + (uint32_t)((kt) & 1) * KVBUF;                         \
    uint32_t vb_ = sV + (uint32_t)((kt) & 1) * KVBUF;                         \
    _Pragma("unroll")                                                         \
    for (int i_ = 0; i_ < 4; i_++) {                                          \
        int c_ = t + i_ * 128;                                                \
        int row_ = c_ >> 3, c8_ = c_ & 7;                                     \
        const h16* gr_ = base + (size_t)((kt) * 64 + row_) * 1536 + c8_ * 8;  \
        cpa16(kb_ + row_ * 144 + c8_ * 16, gr_ + 64);                         \
        cpa16(vb_ + row_ * 144 + c8_ * 16, gr_ + 128);                        \
    }                                                                         \
    cp_commit(); } while (0)

    ISSUE_KV(0);
    cp_wait1(); __syncthreads();   // Q landed, KV0 in flight

    uint32_t qf[2][4][4];
    {
        const int lr = lane & 15, lc = lane >> 4;
#pragma unroll
        for (int mi = 0; mi < 2; mi++)
#pragma unroll
            for (int ks = 0; ks < 4; ks++)
                ldsm4(qf[mi][ks],
                      sQ + (uint32_t)((m0 + mi * 16 + lr) * 144
                                      + (ks * 16 + lc * 8) * 2));
    }

    float o[2][8][4];
#pragma unroll
    for (int a = 0; a < 2; a++)
#pragma unroll
        for (int c = 0; c < 8; c++)
#pragma unroll
            for (int d = 0; d < 4; d++) o[a][c][d] = 0.f;
    float lrow[4] = {0.f, 0.f, 0.f, 0.f};   // per-thread partial row sums

    const int NT = Ss / 64;
    for (int kt = 0; kt < NT; kt++) {
        if (kt + 1 < NT) { ISSUE_KV(kt + 1); cp_wait1(); }
        else cp_wait0();
        __syncthreads();
        const uint32_t kbuf = sK + (uint32_t)(kt & 1) * KVBUF;
        const uint32_t vbuf = sV + (uint32_t)(kt & 1) * KVBUF;

        // S = Q K^T   (logits in log2 domain, Q pre-scaled)
        float sc[2][8][4];
#pragma unroll
        for (int a = 0; a < 2; a++)
#pragma unroll
            for (int c = 0; c < 8; c++)
#pragma unroll
                for (int d = 0; d < 4; d++) sc[a][c][d] = 0.f;

#pragma unroll
        for (int ks = 0; ks < 4; ks++) {
#pragma unroll
            for (int nip = 0; nip < 4; nip++) {
                uint32_t kf[4];
                ldsm4(kf, kbuf + (uint32_t)((nip * 16 + (g8 & 2) * 4 + l8) * 144
                                            + (ks * 16 + (g8 & 1) * 8) * 2));
                uint32_t b0[2] = {kf[0], kf[1]}, b1[2] = {kf[2], kf[3]};
                mma_f16(sc[0][nip * 2],     qf[0][ks], b0);
                mma_f16(sc[0][nip * 2 + 1], qf[0][ks], b1);
                mma_f16(sc[1][nip * 2],     qf[1][ks], b0);
                mma_f16(sc[1][nip * 2 + 1], qf[1][ks], b1);
            }
        }

        // no-max softmax: P = exp2(s); local l accumulation only
#pragma unroll
        for (int mi = 0; mi < 2; mi++)
#pragma unroll
            for (int ni = 0; ni < 8; ni++) {
                float p0 = fexp2(sc[mi][ni][0]);
                float p1 = fexp2(sc[mi][ni][1]);
                float p2 = fexp2(sc[mi][ni][2]);
                float p3 = fexp2(sc[mi][ni][3]);
                sc[mi][ni][0] = p0; sc[mi][ni][1] = p1;
                sc[mi][ni][2] = p2; sc[mi][ni][3] = p3;
                lrow[mi * 2 + 0] += p0 + p1;
                lrow[mi * 2 + 1] += p2 + p3;
            }

        // O += P V  (P packed in registers)
#pragma unroll
        for (int ksv = 0; ksv < 4; ksv++) {
            uint32_t pa[2][4];
#pragma unroll
            for (int mi = 0; mi < 2; mi++) {
                pa[mi][0] = packh(sc[mi][2 * ksv][0],     sc[mi][2 * ksv][1]);
                pa[mi][1] = packh(sc[mi][2 * ksv][2],     sc[mi][2 * ksv][3]);
                pa[mi][2] = packh(sc[mi][2 * ksv + 1][0], sc[mi][2 * ksv + 1][1]);
                pa[mi][3] = packh(sc[mi][2 * ksv + 1][2], sc[mi][2 * ksv + 1][3]);
            }
#pragma unroll
            for (int nip = 0; nip < 4; nip++) {
                uint32_t vf[4];
                ldsm4t(vf, vbuf + (uint32_t)((ksv * 16 + (g8 & 1) * 8 + l8) * 144
                                             + (nip * 16 + (g8 & 2) * 4) * 2));
                uint32_t v0[2] = {vf[0], vf[1]}, v1[2] = {vf[2], vf[3]};
                mma_f16(o[0][nip * 2],     pa[0], v0);
                mma_f16(o[0][nip * 2 + 1], pa[0], v1);
                mma_f16(o[1][nip * 2],     pa[1], v0);
                mma_f16(o[1][nip * 2 + 1], pa[1], v1);
            }
        }
        __syncthreads();   // tile consumed; buffer reusable for kt+2
    }

    // Single cross-lane l reduction (4 lanes of a quad share each row)
#pragma unroll
    for (int slot = 0; slot < 4; slot++) {
        lrow[slot] += __shfl_xor_sync(0xffffffffu, lrow[slot], 1);
        lrow[slot] += __shfl_xor_sync(0xffffffffu, lrow[slot], 2);
    }

    // Epilogue: fp16 out
#pragma unroll
    for (int slot = 0; slot < 4; slot++) {
        const int mi = slot >> 1, hh = slot & 1;
        const int row = m0 + mi * 16 + gid + hh * 8;
        const float inv = 1.f / lrow[slot];
        const size_t gb = ((size_t)b * Ss + q0 + row) * Dd + h * DHh;
#pragma unroll
        for (int ni = 0; ni < 8; ni++) {
            const int col = ni * 8 + tig * 2;
            *(uint32_t*)(atth + gb + col) =
                packh(o[mi][ni][hh * 2] * inv, o[mi][ni][hh * 2 + 1] * inv);
        }
    }
#undef ISSUE_KV
}

// ---------------------------------------------------------------------------
// LayerNorm over D=512, fp32 input: optional fp32 out + fp16 out
// ---------------------------------------------------------------------------
template <bool STORE32>
__global__ __launch_bounds__(128) void ln_kernel(
    const float* __restrict__ in, const float* __restrict__ g,
    const float* __restrict__ b, float* __restrict__ out, h16* __restrict__ oh)
{
    const int row = blockIdx.x;
    const int t   = threadIdx.x;

    float4 v = *(const float4*)(in + (size_t)row * Dd + t * 4);
    float s  = v.x + v.y + v.z + v.w;
    float ss = v.x * v.x + v.y * v.y + v.z * v.z + v.w * v.w;

#pragma unroll
    for (int off = 16; off > 0; off >>= 1) {
        s  += __shfl_xor_sync(0xffffffffu, s, off);
        ss += __shfl_xor_sync(0xffffffffu, ss, off);
    }
    __shared__ float sm_s[4], sm_ss[4];
    if ((t & 31) == 0) { sm_s[t >> 5] = s; sm_ss[t >> 5] = ss; }
    __syncthreads();
    s  = sm_s[0] + sm_s[1] + sm_s[2] + sm_s[3];
    ss = sm_ss[0] + sm_ss[1] + sm_ss[2] + sm_ss[3];

    const float inv_n = 1.f / (float)Dd;
    float mean = s * inv_n;
    float var  = ss * inv_n - mean * mean;
    float rstd = rsqrtf(var + 1e-5f);

    float4 g4 = *(const float4*)(g + t * 4);
    float4 b4 = *(const float4*)(b + t * 4);
    float4 rr;
    rr.x = (v.x - mean) * rstd * g4.x + b4.x;
    rr.y = (v.y - mean) * rstd * g4.y + b4.y;
    rr.z = (v.z - mean) * rstd * g4.z + b4.z;
    rr.w = (v.w - mean) * rstd * g4.w + b4.w;
    if (STORE32)
        *(float4*)(out + (size_t)row * Dd + t * 4) = rr;
    *(uint2*)(oh + (size_t)row * Dd + t * 4) =
        make_uint2(packh(rr.x, rr.y), packh(rr.z, rr.w));
}

// ---------------------------------------------------------------------------
// Launcher
// ---------------------------------------------------------------------------
extern "C" void kernel_launch(void* const* d_in, const int* in_sizes, int n_in,
                              void* d_out, int out_size)
{
    const float* X     = (const float*)d_in[0];
    const float* qkv_w = (const float*)d_in[1];
    const float* qkv_b = (const float*)d_in[2];
    const float* fc_w  = (const float*)d_in[3];
    const float* fc_b  = (const float*)d_in[4];
    const float* ln1_g = (const float*)d_in[5];
    const float* ln1_b = (const float*)d_in[6];
    const float* w1    = (const float*)d_in[7];
    const float* b1    = (const float*)d_in[8];
    const float* w2    = (const float*)d_in[9];
    const float* b2    = (const float*)d_in[10];
    const float* ln2_g = (const float*)d_in[11];
    const float* ln2_b = (const float*)d_in[12];
    float* out = (float*)d_out;

    float *x, *qkvbias;
    h16 *qkvb, *X16, *x16, *xn16, *at16, *h116;
    h16 *qkvT, *fcT, *w1T, *w2T;
    cudaGetSymbolAddress((void**)&x,    g_x);
    cudaGetSymbolAddress((void**)&qkvb, g_qkvb);
    cudaGetSymbolAddress((void**)&qkvbias, g_qkvbias);
    cudaGetSymbolAddress((void**)&X16,  g_X16);
    cudaGetSymbolAddress((void**)&x16,  g_x16);
    cudaGetSymbolAddress((void**)&xn16, g_xn16);
    cudaGetSymbolAddress((void**)&at16, g_at16);
    cudaGetSymbolAddress((void**)&h116, g_h116);
    cudaGetSymbolAddress((void**)&qkvT, g_qkvwT);
    cudaGetSymbolAddress((void**)&fcT,  g_fcwT);
    cudaGetSymbolAddress((void**)&w1T,  g_w1T);
    cudaGetSymbolAddress((void**)&w2T,  g_w2T);

    cudaFuncSetAttribute(attn_v2,
                         cudaFuncAttributeMaxDynamicSharedMemorySize, ATT2_SMEM);
    cudaFuncSetAttribute(gemm_mma<FLAG_OUTH, 128>,
                         cudaFuncAttributeMaxDynamicSharedMemorySize, GEMM_SMEM_128);
    cudaFuncSetAttribute(gemm_mma<FLAG_RELU | FLAG_OUTH, 128>,
                         cudaFuncAttributeMaxDynamicSharedMemorySize, GEMM_SMEM_128);
    cudaFuncSetAttribute(gemm_mma<FLAG_RES, 64>,
                         cudaFuncAttributeMaxDynamicSharedMemorySize, GEMM_SMEM_64);

    // One-time prep (4 launches)
    convert_h_kernel<<<(MTOT * Dd) / 1024, 256>>>(X, X16, MTOT * Dd);
    scale_bias_kernel<<<(NBLK * 1536 + 255) / 256, 256>>>(qkv_b, qkvbias);
    dim3 tb(32, 8);
    transpose_kernel<<<dim3(48, 16, NBLK), tb>>>(qkv_w, qkvT, 512, 1536, 1);
    transpose3_kernel<<<dim3(1280, 1, NBLK), tb>>>(fc_w, w1, w2, fcT, w1T, w2T);

    for (int blk = 0; blk < NBLK; blk++) {
        const float* xin   = (blk == 0) ? X   : x;    // fp32 residual input
        const h16*   xin16 = (blk == 0) ? X16 : x16;  // fp16 A input

        // qkv = x @ qkv_w(+scaled q) + bias -> fp16   [4096, 1536]
        gemm_mma<FLAG_OUTH, 128><<<dim3(12, 32), 256, GEMM_SMEM_128>>>(
            xin16, qkvT + (size_t)blk * 1536 * 512,
            qkvbias + (size_t)blk * 1536, nullptr, nullptr, qkvb, 512, 1536);

        // att = softmax(q k^T) v -> fp16  (3 CTAs/SM)
        attn_v2<<<dim3(Ss / 128, Hh, Bb), 128, ATT2_SMEM>>>(qkvb, at16);

        // x = xin + att @ fc_w + fc_b   (MT=64: 256 CTAs, 2/SM)
        gemm_mma<FLAG_RES, 64><<<dim3(4, 64), 256, GEMM_SMEM_64>>>(
            at16, fcT + (size_t)blk * 512 * 512,
            fc_b + (size_t)blk * 512, xin, x, nullptr, 512, 512);

        // xn16 = ln1(x)  (fp16 only; x preserved as w2 residual)
        ln_kernel<false><<<MTOT, 128>>>(x, ln1_g + (size_t)blk * Dd,
                                        ln1_b + (size_t)blk * Dd, nullptr, xn16);

        // h1 = relu(xn @ w1 + b1) -> fp16
        gemm_mma<FLAG_RELU | FLAG_OUTH, 128><<<dim3(8, 32), 256, GEMM_SMEM_128>>>(
            xn16, w1T + (size_t)blk * 1024 * 512,
            b1 + (size_t)blk * 1024, nullptr, nullptr, h116, 512, 1024);

        // x = x + h1 @ w2 + b2   (MT=64)
        gemm_mma<FLAG_RES, 64><<<dim3(4, 64), 256, GEMM_SMEM_64>>>(
            h116, w2T + (size_t)blk * 512 * 1024,
            b2 + (size_t)blk * 512, x, x, nullptr, 1024, 512);

        // x = ln2(x)   (last block writes straight to d_out; fp16 to x16)
        ln_kernel<true><<<MTOT, 128>>>(x, ln2_g + (size_t)blk * Dd,
                                       ln2_b + (size_t)blk * Dd,
                                       (blk == NBLK - 1) ? out : x, x16);
    }
}

// round 16
// speedup vs baseline: 1.0905x; 1.0905x over previous
#include <cuda_runtime.h>
#include <cuda_fp16.h>
#include <cstdint>
#include <math.h>

typedef __half h16;

// Problem constants
#define Bb   2
#define Ss   2048
#define Dd   512
#define Hh   8
#define DHh  64
#define DHID 1024
#define NBLK 12
#define MTOT (Bb * Ss)      // 4096 rows
// 1/sqrt(512) * log2(e): logits emerge in log2 domain -> bare ex2 in softmax
#define QSCALE 0.06375871648f

#define FLAG_RES  1
#define FLAG_RELU 2
#define FLAG_OUTH 8

// ---------------------------------------------------------------------------
// Scratch (device globals) — fp32 residual stream, fp16 operands
// ---------------------------------------------------------------------------
__device__ float g_x  [MTOT * Dd];           // fp32 residual state
__device__ h16   g_qkvb[MTOT * 3 * Dd];      // fp16 qkv (q pre-scaled by QSCALE)
__device__ float g_qkvbias[NBLK * 3 * Dd];   // scaled qkv bias

__device__ h16 g_X16 [MTOT * Dd];
__device__ h16 g_x16 [MTOT * Dd];
__device__ h16 g_xn16[MTOT * Dd];
__device__ h16 g_at16[MTOT * Dd];
__device__ h16 g_h116[MTOT * DHID];

// Transposed fp16 weights: [blk][N][K]
__device__ h16 g_qkvwT[NBLK * 1536 * 512];
__device__ h16 g_fcwT [NBLK * 512 * 512];
__device__ h16 g_w1T  [NBLK * 1024 * 512];
__device__ h16 g_w2T  [NBLK * 512 * 1024];

// ---------------------------------------------------------------------------
// PTX helpers
// ---------------------------------------------------------------------------
__device__ __forceinline__ uint32_t smem_u32(const void* p) {
    uint32_t a;
    asm("{ .reg .u64 t; cvta.to.shared.u64 t, %1; cvt.u32.u64 %0, t; }"
        : "=r"(a) : "l"(p));
    return a;
}
__device__ __forceinline__ void cpa16(uint32_t s, const void* g) {
    asm volatile("cp.async.ca.shared.global [%0], [%1], 16;" :: "r"(s), "l"(g));
}
__device__ __forceinline__ void cp_commit() {
    asm volatile("cp.async.commit_group;" ::: "memory");
}
__device__ __forceinline__ void cp_wait2() {
    asm volatile("cp.async.wait_group 2;" ::: "memory");
}
__device__ __forceinline__ void cp_wait1() {
    asm volatile("cp.async.wait_group 1;" ::: "memory");
}
__device__ __forceinline__ void cp_wait0() {
    asm volatile("cp.async.wait_group 0;" ::: "memory");
}
__device__ __forceinline__ void ldsm4(uint32_t a[4], uint32_t addr) {
    asm volatile("ldmatrix.sync.aligned.m8n8.x4.shared.b16 {%0,%1,%2,%3}, [%4];"
                 : "=r"(a[0]), "=r"(a[1]), "=r"(a[2]), "=r"(a[3]) : "r"(addr));
}
__device__ __forceinline__ void ldsm4t(uint32_t a[4], uint32_t addr) {
    asm volatile("ldmatrix.sync.aligned.m8n8.x4.trans.shared.b16 {%0,%1,%2,%3}, [%4];"
                 : "=r"(a[0]), "=r"(a[1]), "=r"(a[2]), "=r"(a[3]) : "r"(addr));
}
__device__ __forceinline__ void mma_f16(float c[4], const uint32_t a[4],
                                        const uint32_t b[2]) {
    asm volatile(
        "mma.sync.aligned.m16n8k16.row.col.f32.f16.f16.f32 "
        "{%0,%1,%2,%3}, {%4,%5,%6,%7}, {%8,%9}, {%0,%1,%2,%3};"
        : "+f"(c[0]), "+f"(c[1]), "+f"(c[2]), "+f"(c[3])
        : "r"(a[0]), "r"(a[1]), "r"(a[2]), "r"(a[3]), "r"(b[0]), "r"(b[1]));
}
__device__ __forceinline__ uint32_t packh(float lo, float hi) {
    uint32_t u;
    asm("cvt.rn.f16x2.f32 %0, %1, %2;" : "=r"(u) : "f"(hi), "f"(lo));
    return u;
}
// bare exp2 (logits pre-multiplied by log2e); clamp keeps fp16 P finite
__device__ __forceinline__ float fexp2(float x) {
    float y;
    asm("ex2.approx.f32 %0, %1;" : "=f"(y) : "f"(fminf(x, 14.f)));
    return y;
}

// ---------------------------------------------------------------------------
// Weight transpose to fp16: W[K,N] -> T[N,K], per blockIdx.z.
// qmode: scale q-part columns (n%192 < 64) by QSCALE (qkv only).
// ---------------------------------------------------------------------------
__global__ __launch_bounds__(256) void transpose_kernel(
    const float* __restrict__ W, h16* __restrict__ T, int K, int N, int qmode)
{
    __shared__ float ts[32][33];
    const int z = blockIdx.z;
    W += (size_t)z * K * N;
    T += (size_t)z * N * K;
    const int n0 = blockIdx.x * 32, k0 = blockIdx.y * 32;
    const int tx = threadIdx.x, ty = threadIdx.y;   // (32, 8)
#pragma unroll
    for (int i = 0; i < 4; i++)
        ts[ty + i * 8][tx] = W[(size_t)(k0 + ty + i * 8) * N + n0 + tx];
    __syncthreads();
#pragma unroll
    for (int i = 0; i < 4; i++) {
        int n = n0 + ty + i * 8;
        float v = ts[tx][ty + i * 8];
        if (qmode && (n % 192) < 64) v *= QSCALE;
        T[(size_t)n * K + k0 + tx] = __float2half_rn(v);
    }
}

// Merged transpose for fc/w1/w2, compact tile list (1280 tiles per blk):
//   [0,256): fc 16x16 tiles; [256,768): w1 32x16; [768,1280): w2 16x32
__global__ __launch_bounds__(256) void transpose3_kernel(
    const float* __restrict__ fc_w, const float* __restrict__ w1,
    const float* __restrict__ w2,
    h16* __restrict__ fcT, h16* __restrict__ w1T, h16* __restrict__ w2T)
{
    __shared__ float ts[32][33];
    const int blk = blockIdx.z;
    int id = blockIdx.x;
    const float* W; h16* T; int K, N, n0, k0;
    if (id < 256)      { W = fc_w; T = fcT; K = 512;  N = 512;
                         n0 = (id & 15) * 32;  k0 = (id >> 4) * 32; }
    else if (id < 768) { id -= 256; W = w1; T = w1T; K = 512;  N = 1024;
                         n0 = (id & 31) * 32;  k0 = (id >> 5) * 32; }
    else               { id -= 768; W = w2; T = w2T; K = 1024; N = 512;
                         n0 = (id & 15) * 32;  k0 = (id >> 4) * 32; }
    W += (size_t)blk * K * N;
    T += (size_t)blk * N * K;
    const int tx = threadIdx.x, ty = threadIdx.y;   // (32, 8)
#pragma unroll
    for (int i = 0; i < 4; i++)
        ts[ty + i * 8][tx] = W[(size_t)(k0 + ty + i * 8) * N + n0 + tx];
    __syncthreads();
#pragma unroll
    for (int i = 0; i < 4; i++)
        T[(size_t)(n0 + ty + i * 8) * K + k0 + tx] =
            __float2half_rn(ts[tx][ty + i * 8]);
}

// fp32 -> fp16 (elementwise)
__global__ __launch_bounds__(256) void convert_h_kernel(
    const float* __restrict__ in, h16* __restrict__ h, int n)
{
    int i = (blockIdx.x * 256 + threadIdx.x) * 4;
    if (i >= n) return;
    float4 v = *(const float4*)(in + i);
    *(uint2*)(h + i) = make_uint2(packh(v.x, v.y), packh(v.z, v.w));
}

// qkv bias, q-part scaled
__global__ __launch_bounds__(256) void scale_bias_kernel(
    const float* __restrict__ in, float* __restrict__ out)
{
    int i = blockIdx.x * 256 + threadIdx.x;
    if (i >= NBLK * 1536) return;
    int n = i % 1536;
    out[i] = in[i] * (((n % 192) < 64) ? QSCALE : 1.0f);
}

// ---------------------------------------------------------------------------
// fp16 GEMM via mma.sync, templated M-tile (MT = 128 or 64).
// C[M,N] = A @ W^T + bias (+res fp32)(+relu). A fp16 [M][K]; B fp16 [N][K].
// CTA MT x 128, BK=32, 8 warps (2m x 4n), warp tile (MT/2) x 32.
// smem: 3 stages x {As[MT][40], Bs[128][40]} halves (pitch 80B)
// ---------------------------------------------------------------------------
template <int FLAGS, int MT>
__global__ __launch_bounds__(256, 2) void gemm_mma(
    const h16* __restrict__ A, const h16* __restrict__ B,
    const float* __restrict__ bias, const float* __restrict__ R,
    float* __restrict__ C, h16* __restrict__ Ch, int K, int N)
{
    constexpr int MI  = MT / 32;              // 16-row frags per warp
    constexpr int ASZ = MT * 80;              // A bytes per stage
    constexpr int SSZ = ASZ + 128 * 80;       // stage bytes

    extern __shared__ char smraw[];
    const uint32_t sb = smem_u32(smraw);
    const int t = threadIdx.x, lane = t & 31, wid = t >> 5;
    const int row0 = blockIdx.y * MT, col0 = blockIdx.x * 128;
    const int m0 = (wid >> 2) * (MT / 2), n0 = (wid & 3) * 32;
    const int NI = K >> 5;

    float acc[MI][4][4];
#pragma unroll
    for (int a = 0; a < MI; a++)
#pragma unroll
        for (int b = 0; b < 4; b++)
#pragma unroll
            for (int c = 0; c < 4; c++) acc[a][b][c] = 0.f;

#define ISSUE(i) do {                                                          \
    uint32_t bo = sb + (uint32_t)((i) % 3) * SSZ;                              \
    _Pragma("unroll")                                                          \
    for (int c_ = t; c_ < MT * 4; c_ += 256) {                                 \
        int row_ = c_ >> 2, q_ = c_ & 3;                                       \
        cpa16(bo + row_ * 80 + q_ * 16,                                        \
              A + (size_t)(row0 + row_) * K + (i) * 32 + q_ * 8);              \
    }                                                                          \
    _Pragma("unroll")                                                          \
    for (int c_ = t; c_ < 512; c_ += 256) {                                    \
        int row_ = c_ >> 2, q_ = c_ & 3;                                       \
        cpa16(bo + ASZ + row_ * 80 + q_ * 16,                                  \
              B + (size_t)(col0 + row_) * K + (i) * 32 + q_ * 8);              \
    }                                                                          \
    cp_commit(); } while (0)

    ISSUE(0);
    ISSUE(1);
    for (int i = 0; i < NI; i++) {
        if (i + 2 < NI) { ISSUE(i + 2); cp_wait2(); }
        else if (i + 1 < NI) cp_wait1();
        else cp_wait0();
        __syncthreads();
        const uint32_t bufb = sb + (uint32_t)(i % 3) * SSZ;
#pragma unroll
        for (int ks = 0; ks < 2; ks++) {
            const int kb = ks * 16;
            uint32_t ah[MI][4], bh[4][2];
#pragma unroll
            for (int mi = 0; mi < MI; mi++) {
                uint32_t ad = bufb + (uint32_t)(((m0 + mi * 16 + (lane & 15)) * 40
                                                + kb + (lane >> 4) * 8) * 2);
                ldsm4(ah[mi], ad);
            }
            {
                const int l8 = lane & 7, q = lane >> 3;
                uint32_t bd = bufb + ASZ + (uint32_t)(((n0 + (q >> 1) * 8 + l8) * 40
                                                      + kb + (q & 1) * 8) * 2);
                uint32_t tmp[4];
                ldsm4(tmp, bd);
                bh[0][0] = tmp[0]; bh[0][1] = tmp[1]; bh[1][0] = tmp[2]; bh[1][1] = tmp[3];
                ldsm4(tmp, bd + 16 * 80);
                bh[2][0] = tmp[0]; bh[2][1] = tmp[1]; bh[3][0] = tmp[2]; bh[3][1] = tmp[3];
            }
#pragma unroll
            for (int mi = 0; mi < MI; mi++)
#pragma unroll
                for (int ni = 0; ni < 4; ni++)
                    mma_f16(acc[mi][ni], ah[mi], bh[ni]);
        }
        __syncthreads();
    }
#undef ISSUE

    // Epilogue
    const int gid = lane >> 2, tig = lane & 3;
#pragma unroll
    for (int mi = 0; mi < MI; mi++) {
        const int ra = row0 + m0 + mi * 16 + gid;
#pragma unroll
        for (int ni = 0; ni < 4; ni++) {
            const int col = col0 + n0 + ni * 8 + tig * 2;
            float2 bv = *(const float2*)(bias + col);
            float x0 = acc[mi][ni][0] + bv.x, x1 = acc[mi][ni][1] + bv.y;
            float x2 = acc[mi][ni][2] + bv.x, x3 = acc[mi][ni][3] + bv.y;
            if (FLAGS & FLAG_RES) {
                float2 r0 = *(const float2*)(R + (size_t)ra * N + col);
                float2 r1 = *(const float2*)(R + (size_t)(ra + 8) * N + col);
                x0 += r0.x; x1 += r0.y; x2 += r1.x; x3 += r1.y;
            }
            if (FLAGS & FLAG_RELU) {
                x0 = fmaxf(x0, 0.f); x1 = fmaxf(x1, 0.f);
                x2 = fmaxf(x2, 0.f); x3 = fmaxf(x3, 0.f);
            }
            if (FLAGS & FLAG_OUTH) {
                *(uint32_t*)(Ch + (size_t)ra * N + col) = packh(x0, x1);
                *(uint32_t*)(Ch + (size_t)(ra + 8) * N + col) = packh(x2, x3);
            } else {
                *(float2*)(C + (size_t)ra * N + col) = make_float2(x0, x1);
                *(float2*)(C + (size_t)(ra + 8) * N + col) = make_float2(x2, x3);
            }
        }
    }
}

#define GEMM_SMEM_128 (3 * (128 * 80 + 128 * 80))   // 61440
#define GEMM_SMEM_64  (3 * (64 * 80 + 128 * 80))    // 46080

// ---------------------------------------------------------------------------
// Flash attention: fp16 mma, 4 warps (32 q rows each), double-buffered K/V,
// no-max softmax in log2 domain (bare ex2), single final l reduction.
// Grid (S/128, H, B), 128 threads, 2 CTAs/SM (proven config).
// ---------------------------------------------------------------------------
#define KVBUF 9216                               // 64*144 B
#define ATT2_SMEM (128 * 144 + 4 * KVBUF)        // 55296

__global__ __launch_bounds__(128, 2) void attn_v2(
    const h16* __restrict__ qkvb, h16* __restrict__ atth)
{
    extern __shared__ char smc[];
    const uint32_t sQ = smem_u32(smc);
    const uint32_t sK = sQ + 128 * 144;          // 2 buffers
    const uint32_t sV = sK + 2 * KVBUF;          // 2 buffers

    const int t = threadIdx.x, lane = t & 31, wid = t >> 5;
    const int gid = lane >> 2, tig = lane & 3;
    const int l8 = lane & 7, g8 = lane >> 3;
    const int q0 = blockIdx.x * 128, h = blockIdx.y, b = blockIdx.z;
    const int m0 = wid * 32;
    const h16* base = qkvb + (size_t)b * Ss * 1536 + h * 192;

    // Q prologue
#pragma unroll
    for (int i = 0; i < 8; i++) {
        int c = t + i * 128;
        int row = c >> 3, c8 = c & 7;
        cpa16(sQ + row * 144 + c8 * 16,
              base + (size_t)(q0 + row) * 1536 + c8 * 8);
    }
    cp_commit();

#define ISSUE_KV(kt) do {                                                     \
    uint32_t kb_ = sK + (uint32_t)((kt) & 1) * KVBUF;                         \
    uint32_t vb_ = sV + (uint32_t)((kt) & 1) * KVBUF;                         \
    _Pragma("unroll")                                                         \
    for (int i_ = 0; i_ < 4; i_++) {                                          \
        int c_ = t + i_ * 128;                                                \
        int row_ = c_ >> 3, c8_ = c_ & 7;                                     \
        const h16* gr_ = base + (size_t)((kt) * 64 + row_) * 1536 + c8_ * 8;  \
        cpa16(kb_ + row_ * 144 + c8_ * 16, gr_ + 64);                         \
        cpa16(vb_ + row_ * 144 + c8_ * 16, gr_ + 128);                        \
    }                                                                         \
    cp_commit(); } while (0)

    ISSUE_KV(0);
    cp_wait1(); __syncthreads();   // Q landed, KV0 in flight

    uint32_t qf[2][4][4];
    {
        const int lr = lane & 15, lc = lane >> 4;
#pragma unroll
        for (int mi = 0; mi < 2; mi++)
#pragma unroll
            for (int ks = 0; ks < 4; ks++)
                ldsm4(qf[mi][ks],
                      sQ + (uint32_t)((m0 + mi * 16 + lr) * 144
                                      + (ks * 16 + lc * 8) * 2));
    }

    float o[2][8][4];
#pragma unroll
    for (int a = 0; a < 2; a++)
#pragma unroll
        for (int c = 0; c < 8; c++)
#pragma unroll
            for (int d = 0; d < 4; d++) o[a][c][d] = 0.f;
    float lrow[4] = {0.f, 0.f, 0.f, 0.f};   // per-thread partial row sums

    const int NT = Ss / 64;
    for (int kt = 0; kt < NT; kt++) {
        if (kt + 1 < NT) { ISSUE_KV(kt + 1); cp_wait1(); }
        else cp_wait0();
        __syncthreads();
        const uint32_t kbuf = sK + (uint32_t)(kt & 1) * KVBUF;
        const uint32_t vbuf = sV + (uint32_t)(kt & 1) * KVBUF;

        // S = Q K^T   (logits in log2 domain, Q pre-scaled)
        float sc[2][8][4];
#pragma unroll
        for (int a = 0; a < 2; a++)
#pragma unroll
            for (int c = 0; c < 8; c++)
#pragma unroll
                for (int d = 0; d < 4; d++) sc[a][c][d] = 0.f;

#pragma unroll
        for (int ks = 0; ks < 4; ks++) {
#pragma unroll
            for (int nip = 0; nip < 4; nip++) {
                uint32_t kf[4];
                ldsm4(kf, kbuf + (uint32_t)((nip * 16 + (g8 & 2) * 4 + l8) * 144
                                            + (ks * 16 + (g8 & 1) * 8) * 2));
                uint32_t b0[2] = {kf[0], kf[1]}, b1[2] = {kf[2], kf[3]};
                mma_f16(sc[0][nip * 2],     qf[0][ks], b0);
                mma_f16(sc[0][nip * 2 + 1], qf[0][ks], b1);
                mma_f16(sc[1][nip * 2],     qf[1][ks], b0);
                mma_f16(sc[1][nip * 2 + 1], qf[1][ks], b1);
            }
        }

        // no-max softmax: P = exp2(s); local l accumulation only
#pragma unroll
        for (int mi = 0; mi < 2; mi++)
#pragma unroll
            for (int ni = 0; ni < 8; ni++) {
                float p0 = fexp2(sc[mi][ni][0]);
                float p1 = fexp2(sc[mi][ni][1]);
                float p2 = fexp2(sc[mi][ni][2]);
                float p3 = fexp2(sc[mi][ni][3]);
                sc[mi][ni][0] = p0; sc[mi][ni][1] = p1;
                sc[mi][ni][2] = p2; sc[mi][ni][3] = p3;
                lrow[mi * 2 + 0] += p0 + p1;
                lrow[mi * 2 + 1] += p2 + p3;
            }

        // O += P V  (P packed in registers)
#pragma unroll
        for (int ksv = 0; ksv < 4; ksv++) {
            uint32_t pa[2][4];
#pragma unroll
            for (int mi = 0; mi < 2; mi++) {
                pa[mi][0] = packh(sc[mi][2 * ksv][0],     sc[mi][2 * ksv][1]);
                pa[mi][1] = packh(sc[mi][2 * ksv][2],     sc[mi][2 * ksv][3]);
                pa[mi][2] = packh(sc[mi][2 * ksv + 1][0], sc[mi][2 * ksv + 1][1]);
                pa[mi][3] = packh(sc[mi][2 * ksv + 1][2], sc[mi][2 * ksv + 1][3]);
            }
#pragma unroll
            for (int nip = 0; nip < 4; nip++) {
                uint32_t vf[4];
                ldsm4t(vf, vbuf + (uint32_t)((ksv * 16 + (g8 & 1) * 8 + l8) * 144
                                             + (nip * 16 + (g8 & 2) * 4) * 2));
                uint32_t v0[2] = {vf[0], vf[1]}, v1[2] = {vf[2], vf[3]};
                mma_f16(o[0][nip * 2],     pa[0], v0);
                mma_f16(o[0][nip * 2 + 1], pa[0], v1);
                mma_f16(o[1][nip * 2],     pa[1], v0);
                mma_f16(o[1][nip * 2 + 1], pa[1], v1);
            }
        }
        __syncthreads();   // tile consumed; buffer reusable for kt+2
    }

    // Single cross-lane l reduction (4 lanes of a quad share each row)
#pragma unroll
    for (int slot = 0; slot < 4; slot++) {
        lrow[slot] += __shfl_xor_sync(0xffffffffu, lrow[slot], 1);
        lrow[slot] += __shfl_xor_sync(0xffffffffu, lrow[slot], 2);
    }

    // Epilogue: fp16 out
#pragma unroll
    for (int slot = 0; slot < 4; slot++) {
        const int mi = slot >> 1, hh = slot & 1;
        const int row = m0 + mi * 16 + gid + hh * 8;
        const float inv = 1.f / lrow[slot];
        const size_t gb = ((size_t)b * Ss + q0 + row) * Dd + h * DHh;
#pragma unroll
        for (int ni = 0; ni < 8; ni++) {
            const int col = ni * 8 + tig * 2;
            *(uint32_t*)(atth + gb + col) =
                packh(o[mi][ni][hh * 2] * inv, o[mi][ni][hh * 2 + 1] * inv);
        }
    }
#undef ISSUE_KV
}

// ---------------------------------------------------------------------------
// LayerNorm over D=512, fp32 input: optional fp32 out + fp16 out
// ---------------------------------------------------------------------------
template <bool STORE32>
__global__ __launch_bounds__(128) void ln_kernel(
    const float* __restrict__ in, const float* __restrict__ g,
    const float* __restrict__ b, float* __restrict__ out, h16* __restrict__ oh)
{
    const int row = blockIdx.x;
    const int t   = threadIdx.x;

    float4 v = *(const float4*)(in + (size_t)row * Dd + t * 4);
    float s  = v.x + v.y + v.z + v.w;
    float ss = v.x * v.x + v.y * v.y + v.z * v.z + v.w * v.w;

#pragma unroll
    for (int off = 16; off > 0; off >>= 1) {
        s  += __shfl_xor_sync(0xffffffffu, s, off);
        ss += __shfl_xor_sync(0xffffffffu, ss, off);
    }
    __shared__ float sm_s[4], sm_ss[4];
    if ((t & 31) == 0) { sm_s[t >> 5] = s; sm_ss[t >> 5] = ss; }
    __syncthreads();
    s  = sm_s[0] + sm_s[1] + sm_s[2] + sm_s[3];
    ss = sm_ss[0] + sm_ss[1] + sm_ss[2] + sm_ss[3];

    const float inv_n = 1.f / (float)Dd;
    float mean = s * inv_n;
    float var  = ss * inv_n - mean * mean;
    float rstd = rsqrtf(var + 1e-5f);

    float4 g4 = *(const float4*)(g + t * 4);
    float4 b4 = *(const float4*)(b + t * 4);
    float4 rr;
    rr.x = (v.x - mean) * rstd * g4.x + b4.x;
    rr.y = (v.y - mean) * rstd * g4.y + b4.y;
    rr.z = (v.z - mean) * rstd * g4.z + b4.z;
    rr.w = (v.w - mean) * rstd * g4.w + b4.w;
    if (STORE32)
        *(float4*)(out + (size_t)row * Dd + t * 4) = rr;
    *(uint2*)(oh + (size_t)row * Dd + t * 4) =
        make_uint2(packh(rr.x, rr.y), packh(rr.z, rr.w));
}

// ---------------------------------------------------------------------------
// Launcher
// ---------------------------------------------------------------------------
extern "C" void kernel_launch(void* const* d_in, const int* in_sizes, int n_in,
                              void* d_out, int out_size)
{
    const float* X     = (const float*)d_in[0];
    const float* qkv_w = (const float*)d_in[1];
    const float* qkv_b = (const float*)d_in[2];
    const float* fc_w  = (const float*)d_in[3];
    const float* fc_b  = (const float*)d_in[4];
    const float* ln1_g = (const float*)d_in[5];
    const float* ln1_b = (const float*)d_in[6];
    const float* w1    = (const float*)d_in[7];
    const float* b1    = (const float*)d_in[8];
    const float* w2    = (const float*)d_in[9];
    const float* b2    = (const float*)d_in[10];
    const float* ln2_g = (const float*)d_in[11];
    const float* ln2_b = (const float*)d_in[12];
    float* out = (float*)d_out;

    float *x, *qkvbias;
    h16 *qkvb, *X16, *x16, *xn16, *at16, *h116;
    h16 *qkvT, *fcT, *w1T, *w2T;
    cudaGetSymbolAddress((void**)&x,    g_x);
    cudaGetSymbolAddress((void**)&qkvb, g_qkvb);
    cudaGetSymbolAddress((void**)&qkvbias, g_qkvbias);
    cudaGetSymbolAddress((void**)&X16,  g_X16);
    cudaGetSymbolAddress((void**)&x16,  g_x16);
    cudaGetSymbolAddress((void**)&xn16, g_xn16);
    cudaGetSymbolAddress((void**)&at16, g_at16);
    cudaGetSymbolAddress((void**)&h116, g_h116);
    cudaGetSymbolAddress((void**)&qkvT, g_qkvwT);
    cudaGetSymbolAddress((void**)&fcT,  g_fcwT);
    cudaGetSymbolAddress((void**)&w1T,  g_w1T);
    cudaGetSymbolAddress((void**)&w2T,  g_w2T);

    cudaFuncSetAttribute(attn_v2,
                         cudaFuncAttributeMaxDynamicSharedMemorySize, ATT2_SMEM);
    cudaFuncSetAttribute(gemm_mma<FLAG_OUTH, 128>,
                         cudaFuncAttributeMaxDynamicSharedMemorySize, GEMM_SMEM_128);
    cudaFuncSetAttribute(gemm_mma<FLAG_RELU | FLAG_OUTH, 128>,
                         cudaFuncAttributeMaxDynamicSharedMemorySize, GEMM_SMEM_128);
    cudaFuncSetAttribute(gemm_mma<FLAG_RES, 64>,
                         cudaFuncAttributeMaxDynamicSharedMemorySize, GEMM_SMEM_64);

    // One-time prep (4 launches)
    convert_h_kernel<<<(MTOT * Dd) / 1024, 256>>>(X, X16, MTOT * Dd);
    scale_bias_kernel<<<(NBLK * 1536 + 255) / 256, 256>>>(qkv_b, qkvbias);
    dim3 tb(32, 8);
    transpose_kernel<<<dim3(48, 16, NBLK), tb>>>(qkv_w, qkvT, 512, 1536, 1);
    transpose3_kernel<<<dim3(1280, 1, NBLK), tb>>>(fc_w, w1, w2, fcT, w1T, w2T);

    for (int blk = 0; blk < NBLK; blk++) {
        const float* xin   = (blk == 0) ? X   : x;    // fp32 residual input
        const h16*   xin16 = (blk == 0) ? X16 : x16;  // fp16 A input

        // qkv = x @ qkv_w(+scaled q) + bias -> fp16   [4096, 1536]
        gemm_mma<FLAG_OUTH, 128><<<dim3(12, 32), 256, GEMM_SMEM_128>>>(
            xin16, qkvT + (size_t)blk * 1536 * 512,
            qkvbias + (size_t)blk * 1536, nullptr, nullptr, qkvb, 512, 1536);

        // att = softmax(q k^T) v -> fp16  (2 CTAs/SM, proven)
        attn_v2<<<dim3(Ss / 128, Hh, Bb), 128, ATT2_SMEM>>>(qkvb, at16);

        // x = xin + att @ fc_w + fc_b   (MT=64: 256 CTAs, 2/SM)
        gemm_mma<FLAG_RES, 64><<<dim3(4, 64), 256, GEMM_SMEM_64>>>(
            at16, fcT + (size_t)blk * 512 * 512,
            fc_b + (size_t)blk * 512, xin, x, nullptr, 512, 512);

        // xn16 = ln1(x)  (fp16 only; x preserved as w2 residual)
        ln_kernel<false><<<MTOT, 128>>>(x, ln1_g + (size_t)blk * Dd,
                                        ln1_b + (size_t)blk * Dd, nullptr, xn16);

        // h1 = relu(xn @ w1 + b1) -> fp16
        gemm_mma<FLAG_RELU | FLAG_OUTH, 128><<<dim3(8, 32), 256, GEMM_SMEM_128>>>(
            xn16, w1T + (size_t)blk * 1024 * 512,
            b1 + (size_t)blk * 1024, nullptr, nullptr, h116, 512, 1024);

        // x = x + h1 @ w2 + b2   (MT=64)
        gemm_mma<FLAG_RES, 64><<<dim3(4, 64), 256, GEMM_SMEM_64>>>(
            h116, w2T + (size_t)blk * 512 * 1024,
            b2 + (size_t)blk * 512, x, x, nullptr, 1024, 512);

        // x = ln2(x)   (last block writes straight to d_out; fp16 to x16)
        ln_kernel<true><<<MTOT, 128>>>(x, ln2_g + (size_t)blk * Dd,
                                       ln2_b + (size_t)blk * Dd,
                                       (blk == NBLK - 1) ? out : x, x16);
    }
}

// round 17
// speedup vs baseline: 1.0931x; 1.0024x over previous
#include <cuda_runtime.h>
#include <cuda_fp16.h>
#include <cstdint>
#include <math.h>

typedef __half h16;

// Problem constants
#define Bb   2
#define Ss   2048
#define Dd   512
#define Hh   8
#define DHh  64
#define DHID 1024
#define NBLK 12
#define MTOT (Bb * Ss)      // 4096 rows
// 1/sqrt(512) * log2(e): logits emerge in log2 domain -> bare ex2 in softmax
#define QSCALE 0.06375871648f

#define FLAG_RES  1
#define FLAG_RELU 2
#define FLAG_OUTH 8

// ---------------------------------------------------------------------------
// Scratch (device globals) — fp32 residual stream, fp16 operands
// ---------------------------------------------------------------------------
__device__ float g_x  [MTOT * Dd];           // fp32 residual state
__device__ h16   g_qkvb[MTOT * 3 * Dd];      // fp16 qkv (q pre-scaled by QSCALE)
__device__ float g_qkvbias[NBLK * 3 * Dd];   // scaled qkv bias

__device__ h16 g_X16 [MTOT * Dd];
__device__ h16 g_x16 [MTOT * Dd];
__device__ h16 g_xn16[MTOT * Dd];
__device__ h16 g_at16[MTOT * Dd];
__device__ h16 g_h116[MTOT * DHID];

// Transposed fp16 weights: [blk][N][K]
__device__ h16 g_qkvwT[NBLK * 1536 * 512];
__device__ h16 g_fcwT [NBLK * 512 * 512];
__device__ h16 g_w1T  [NBLK * 1024 * 512];
__device__ h16 g_w2T  [NBLK * 512 * 1024];

// ---------------------------------------------------------------------------
// PTX helpers
// ---------------------------------------------------------------------------
__device__ __forceinline__ uint32_t smem_u32(const void* p) {
    uint32_t a;
    asm("{ .reg .u64 t; cvta.to.shared.u64 t, %1; cvt.u32.u64 %0, t; }"
        : "=r"(a) : "l"(p));
    return a;
}
__device__ __forceinline__ void cpa16(uint32_t s, const void* g) {
    asm volatile("cp.async.ca.shared.global [%0], [%1], 16;" :: "r"(s), "l"(g));
}
__device__ __forceinline__ void cp_commit() {
    asm volatile("cp.async.commit_group;" ::: "memory");
}
__device__ __forceinline__ void cp_wait2() {
    asm volatile("cp.async.wait_group 2;" ::: "memory");
}
__device__ __forceinline__ void cp_wait1() {
    asm volatile("cp.async.wait_group 1;" ::: "memory");
}
__device__ __forceinline__ void cp_wait0() {
    asm volatile("cp.async.wait_group 0;" ::: "memory");
}
__device__ __forceinline__ void ldsm4(uint32_t a[4], uint32_t addr) {
    asm volatile("ldmatrix.sync.aligned.m8n8.x4.shared.b16 {%0,%1,%2,%3}, [%4];"
                 : "=r"(a[0]), "=r"(a[1]), "=r"(a[2]), "=r"(a[3]) : "r"(addr));
}
__device__ __forceinline__ void ldsm4t(uint32_t a[4], uint32_t addr) {
    asm volatile("ldmatrix.sync.aligned.m8n8.x4.trans.shared.b16 {%0,%1,%2,%3}, [%4];"
                 : "=r"(a[0]), "=r"(a[1]), "=r"(a[2]), "=r"(a[3]) : "r"(addr));
}
__device__ __forceinline__ void mma_f16(float c[4], const uint32_t a[4],
                                        const uint32_t b[2]) {
    asm volatile(
        "mma.sync.aligned.m16n8k16.row.col.f32.f16.f16.f32 "
        "{%0,%1,%2,%3}, {%4,%5,%6,%7}, {%8,%9}, {%0,%1,%2,%3};"
        : "+f"(c[0]), "+f"(c[1]), "+f"(c[2]), "+f"(c[3])
        : "r"(a[0]), "r"(a[1]), "r"(a[2]), "r"(a[3]), "r"(b[0]), "r"(b[1]));
}
__device__ __forceinline__ uint32_t packh(float lo, float hi) {
    uint32_t u;
    asm("cvt.rn.f16x2.f32 %0, %1, %2;" : "=r"(u) : "f"(hi), "f"(lo));
    return u;
}
// bare exp2 (logits pre-multiplied by log2e); clamp keeps fp16 P finite
__device__ __forceinline__ float fexp2(float x) {
    float y;
    asm("ex2.approx.f32 %0, %1;" : "=f"(y) : "f"(fminf(x, 14.f)));
    return y;
}

// ---------------------------------------------------------------------------
// Weight transpose to fp16: W[K,N] -> T[N,K], per blockIdx.z.
// qmode: scale q-part columns (n%192 < 64) by QSCALE (qkv only).
// ---------------------------------------------------------------------------
__global__ __launch_bounds__(256) void transpose_kernel(
    const float* __restrict__ W, h16* __restrict__ T, int K, int N, int qmode)
{
    __shared__ float ts[32][33];
    const int z = blockIdx.z;
    W += (size_t)z * K * N;
    T += (size_t)z * N * K;
    const int n0 = blockIdx.x * 32, k0 = blockIdx.y * 32;
    const int tx = threadIdx.x, ty = threadIdx.y;   // (32, 8)
#pragma unroll
    for (int i = 0; i < 4; i++)
        ts[ty + i * 8][tx] = W[(size_t)(k0 + ty + i * 8) * N + n0 + tx];
    __syncthreads();
#pragma unroll
    for (int i = 0; i < 4; i++) {
        int n = n0 + ty + i * 8;
        float v = ts[tx][ty + i * 8];
        if (qmode && (n % 192) < 64) v *= QSCALE;
        T[(size_t)n * K + k0 + tx] = __float2half_rn(v);
    }
}

// Merged transpose for fc/w1/w2, compact tile list (1280 tiles per blk):
//   [0,256): fc 16x16 tiles; [256,768): w1 32x16; [768,1280): w2 16x32
__global__ __launch_bounds__(256) void transpose3_kernel(
    const float* __restrict__ fc_w, const float* __restrict__ w1,
    const float* __restrict__ w2,
    h16* __restrict__ fcT, h16* __restrict__ w1T, h16* __restrict__ w2T)
{
    __shared__ float ts[32][33];
    const int blk = blockIdx.z;
    int id = blockIdx.x;
    const float* W; h16* T; int K, N, n0, k0;
    if (id < 256)      { W = fc_w; T = fcT; K = 512;  N = 512;
                         n0 = (id & 15) * 32;  k0 = (id >> 4) * 32; }
    else if (id < 768) { id -= 256; W = w1; T = w1T; K = 512;  N = 1024;
                         n0 = (id & 31) * 32;  k0 = (id >> 5) * 32; }
    else               { id -= 768; W = w2; T = w2T; K = 1024; N = 512;
                         n0 = (id & 15) * 32;  k0 = (id >> 4) * 32; }
    W += (size_t)blk * K * N;
    T += (size_t)blk * N * K;
    const int tx = threadIdx.x, ty = threadIdx.y;   // (32, 8)
#pragma unroll
    for (int i = 0; i < 4; i++)
        ts[ty + i * 8][tx] = W[(size_t)(k0 + ty + i * 8) * N + n0 + tx];
    __syncthreads();
#pragma unroll
    for (int i = 0; i < 4; i++)
        T[(size_t)(n0 + ty + i * 8) * K + k0 + tx] =
            __float2half_rn(ts[tx][ty + i * 8]);
}

// fp32 -> fp16 (elementwise)
__global__ __launch_bounds__(256) void convert_h_kernel(
    const float* __restrict__ in, h16* __restrict__ h, int n)
{
    int i = (blockIdx.x * 256 + threadIdx.x) * 4;
    if (i >= n) return;
    float4 v = *(const float4*)(in + i);
    *(uint2*)(h + i) = make_uint2(packh(v.x, v.y), packh(v.z, v.w));
}

// qkv bias, q-part scaled
__global__ __launch_bounds__(256) void scale_bias_kernel(
    const float* __restrict__ in, float* __restrict__ out)
{
    int i = blockIdx.x * 256 + threadIdx.x;
    if (i >= NBLK * 1536) return;
    int n = i % 1536;
    out[i] = in[i] * (((n % 192) < 64) ? QSCALE : 1.0f);
}

// ---------------------------------------------------------------------------
// fp16 GEMM via mma.sync, templated M-tile (MT = 128 or 64).
// C[M,N] = A @ W^T + bias (+res fp32)(+relu). A fp16 [M][K]; B fp16 [N][K].
// CTA MT x 128, BK=32, 8 warps (2m x 4n), warp tile (MT/2) x 32.
// smem: 3 stages x {As[MT][40], Bs[128][40]} halves (pitch 80B)
// ---------------------------------------------------------------------------
template <int FLAGS, int MT>
__global__ __launch_bounds__(256, 2) void gemm_mma(
    const h16* __restrict__ A, const h16* __restrict__ B,
    const float* __restrict__ bias, const float* __restrict__ R,
    float* __restrict__ C, h16* __restrict__ Ch, int K, int N)
{
    constexpr int MI  = MT / 32;              // 16-row frags per warp
    constexpr int ASZ = MT * 80;              // A bytes per stage
    constexpr int SSZ = ASZ + 128 * 80;       // stage bytes

    extern __shared__ char smraw[];
    const uint32_t sb = smem_u32(smraw);
    const int t = threadIdx.x, lane = t & 31, wid = t >> 5;
    const int row0 = blockIdx.y * MT, col0 = blockIdx.x * 128;
    const int m0 = (wid >> 2) * (MT / 2), n0 = (wid & 3) * 32;
    const int NI = K >> 5;

    float acc[MI][4][4];
#pragma unroll
    for (int a = 0; a < MI; a++)
#pragma unroll
        for (int b = 0; b < 4; b++)
#pragma unroll
            for (int c = 0; c < 4; c++) acc[a][b][c] = 0.f;

#define ISSUE(i) do {                                                          \
    uint32_t bo = sb + (uint32_t)((i) % 3) * SSZ;                              \
    _Pragma("unroll")                                                          \
    for (int c_ = t; c_ < MT * 4; c_ += 256) {                                 \
        int row_ = c_ >> 2, q_ = c_ & 3;                                       \
        cpa16(bo + row_ * 80 + q_ * 16,                                        \
              A + (size_t)(row0 + row_) * K + (i) * 32 + q_ * 8);              \
    }                                                                          \
    _Pragma("unroll")                                                          \
    for (int c_ = t; c_ < 512; c_ += 256) {                                    \
        int row_ = c_ >> 2, q_ = c_ & 3;                                       \
        cpa16(bo + ASZ + row_ * 80 + q_ * 16,                                  \
              B + (size_t)(col0 + row_) * K + (i) * 32 + q_ * 8);              \
    }                                                                          \
    cp_commit(); } while (0)

    ISSUE(0);
    ISSUE(1);
    for (int i = 0; i < NI; i++) {
        if (i + 2 < NI) { ISSUE(i + 2); cp_wait2(); }
        else if (i + 1 < NI) cp_wait1();
        else cp_wait0();
        __syncthreads();
        const uint32_t bufb = sb + (uint32_t)(i % 3) * SSZ;
#pragma unroll
        for (int ks = 0; ks < 2; ks++) {
            const int kb = ks * 16;
            uint32_t ah[MI][4], bh[4][2];
#pragma unroll
            for (int mi = 0; mi < MI; mi++) {
                uint32_t ad = bufb + (uint32_t)(((m0 + mi * 16 + (lane & 15)) * 40
                                                + kb + (lane >> 4) * 8) * 2);
                ldsm4(ah[mi], ad);
            }
            {
                const int l8 = lane & 7, q = lane >> 3;
                uint32_t bd = bufb + ASZ + (uint32_t)(((n0 + (q >> 1) * 8 + l8) * 40
                                                      + kb + (q & 1) * 8) * 2);
                uint32_t tmp[4];
                ldsm4(tmp, bd);
                bh[0][0] = tmp[0]; bh[0][1] = tmp[1]; bh[1][0] = tmp[2]; bh[1][1] = tmp[3];
                ldsm4(tmp, bd + 16 * 80);
                bh[2][0] = tmp[0]; bh[2][1] = tmp[1]; bh[3][0] = tmp[2]; bh[3][1] = tmp[3];
            }
#pragma unroll
            for (int mi = 0; mi < MI; mi++)
#pragma unroll
                for (int ni = 0; ni < 4; ni++)
                    mma_f16(acc[mi][ni], ah[mi], bh[ni]);
        }
        __syncthreads();
    }
#undef ISSUE

    // Epilogue
    const int gid = lane >> 2, tig = lane & 3;
#pragma unroll
    for (int mi = 0; mi < MI; mi++) {
        const int ra = row0 + m0 + mi * 16 + gid;
#pragma unroll
        for (int ni = 0; ni < 4; ni++) {
            const int col = col0 + n0 + ni * 8 + tig * 2;
            float2 bv = *(const float2*)(bias + col);
            float x0 = acc[mi][ni][0] + bv.x, x1 = acc[mi][ni][1] + bv.y;
            float x2 = acc[mi][ni][2] + bv.x, x3 = acc[mi][ni][3] + bv.y;
            if (FLAGS & FLAG_RES) {
                float2 r0 = *(const float2*)(R + (size_t)ra * N + col);
                float2 r1 = *(const float2*)(R + (size_t)(ra + 8) * N + col);
                x0 += r0.x; x1 += r0.y; x2 += r1.x; x3 += r1.y;
            }
            if (FLAGS & FLAG_RELU) {
                x0 = fmaxf(x0, 0.f); x1 = fmaxf(x1, 0.f);
                x2 = fmaxf(x2, 0.f); x3 = fmaxf(x3, 0.f);
            }
            if (FLAGS & FLAG_OUTH) {
                *(uint32_t*)(Ch + (size_t)ra * N + col) = packh(x0, x1);
                *(uint32_t*)(Ch + (size_t)(ra + 8) * N + col) = packh(x2, x3);
            } else {
                *(float2*)(C + (size_t)ra * N + col) = make_float2(x0, x1);
                *(float2*)(C + (size_t)(ra + 8) * N + col) = make_float2(x2, x3);
            }
        }
    }
}

#define GEMM_SMEM_128 (3 * (128 * 80 + 128 * 80))   // 61440
#define GEMM_SMEM_64  (3 * (64 * 80 + 128 * 80))    // 46080

// ---------------------------------------------------------------------------
// Flash attention: fp16 mma, 4 warps (32 q rows each), double-buffered K/V,
// no-max softmax in log2 domain (bare ex2), single final l reduction.
// Grid (S/128, H, B), 128 threads, 2 CTAs/SM (proven config).
// ---------------------------------------------------------------------------
#define KVBUF 9216                               // 64*144 B
#define ATT2_SMEM (128 * 144 + 4 * KVBUF)        // 55296

__global__ __launch_bounds__(128, 2) void attn_v2(
    const h16* __restrict__ qkvb, h16* __restrict__ atth)
{
    extern __shared__ char smc[];
    const uint32_t sQ = smem_u32(smc);
    const uint32_t sK = sQ + 128 * 144;          // 2 buffers
    const uint32_t sV = sK + 2 * KVBUF;          // 2 buffers

    const int t = threadIdx.x, lane = t & 31, wid = t >> 5;
    const int gid = lane >> 2, tig = lane & 3;
    const int l8 = lane & 7, g8 = lane >> 3;
    const int q0 = blockIdx.x * 128, h = blockIdx.y, b = blockIdx.z;
    const int m0 = wid * 32;
    const h16* base = qkvb + (size_t)b * Ss * 1536 + h * 192;

    // Q prologue
#pragma unroll
    for (int i = 0; i < 8; i++) {
        int c = t + i * 128;
        int row = c >> 3, c8 = c & 7;
        cpa16(sQ + row * 144 + c8 * 16,
              base + (size_t)(q0 + row) * 1536 + c8 * 8);
    }
    cp_commit();

#define ISSUE_KV(kt) do {                                                     \
    uint32_t kb_ = sK + (uint32_t)((kt) & 1) * KVBUF;                         \
    uint32_t vb_ = sV + (uint32_t)((kt) & 1) * KVBUF;                         \
    _Pragma("unroll")                                                         \
    for (int i_ = 0; i_ < 4; i_++) {                                          \
        int c_ = t + i_ * 128;                                                \
        int row_ = c_ >> 3, c8_ = c_ & 7;                                     \
        const h16* gr_ = base + (size_t)((kt) * 64 + row_) * 1536 + c8_ * 8;  \
        cpa16(kb_ + row_ * 144 + c8_ * 16, gr_ + 64);                         \
        cpa16(vb_ + row_ * 144 + c8_ * 16, gr_ + 128);                        \
    }                                                                         \
    cp_commit(); } while (0)

    ISSUE_KV(0);
    cp_wait1(); __syncthreads();   // Q landed, KV0 in flight

    uint32_t qf[2][4][4];
    {
        const int lr = lane & 15, lc = lane >> 4;
#pragma unroll
        for (int mi = 0; mi < 2; mi++)
#pragma unroll
            for (int ks = 0; ks < 4; ks++)
                ldsm4(qf[mi][ks],
                      sQ + (uint32_t)((m0 + mi * 16 + lr) * 144
                                      + (ks * 16 + lc * 8) * 2));
    }

    float o[2][8][4];
#pragma unroll
    for (int a = 0; a < 2; a++)
#pragma unroll
        for (int c = 0; c < 8; c++)
#pragma unroll
            for (int d = 0; d < 4; d++) o[a][c][d] = 0.f;
    float lrow[4] = {0.f, 0.f, 0.f, 0.f};   // per-thread partial row sums

    const int NT = Ss / 64;
    for (int kt = 0; kt < NT; kt++) {
        if (kt + 1 < NT) { ISSUE_KV(kt + 1); cp_wait1(); }
        else cp_wait0();
        __syncthreads();
        const uint32_t kbuf = sK + (uint32_t)(kt & 1) * KVBUF;
        const uint32_t vbuf = sV + (uint32_t)(kt & 1) * KVBUF;

        // S = Q K^T   (logits in log2 domain, Q pre-scaled)
        float sc[2][8][4];
#pragma unroll
        for (int a = 0; a < 2; a++)
#pragma unroll
            for (int c = 0; c < 8; c++)
#pragma unroll
                for (int d = 0; d < 4; d++) sc[a][c][d] = 0.f;

#pragma unroll
        for (int ks = 0; ks < 4; ks++) {
#pragma unroll
            for (int nip = 0; nip < 4; nip++) {
                uint32_t kf[4];
                ldsm4(kf, kbuf + (uint32_t)((nip * 16 + (g8 & 2) * 4 + l8) * 144
                                            + (ks * 16 + (g8 & 1) * 8) * 2));
                uint32_t b0[2] = {kf[0], kf[1]}, b1[2] = {kf[2], kf[3]};
                mma_f16(sc[0][nip * 2],     qf[0][ks], b0);
                mma_f16(sc[0][nip * 2 + 1], qf[0][ks], b1);
                mma_f16(sc[1][nip * 2],     qf[1][ks], b0);
                mma_f16(sc[1][nip * 2 + 1], qf[1][ks], b1);
            }
        }

        // no-max softmax: P = exp2(s); local l accumulation only
#pragma unroll
        for (int mi = 0; mi < 2; mi++)
#pragma unroll
            for (int ni = 0; ni < 8; ni++) {
                float p0 = fexp2(sc[mi][ni][0]);
                float p1 = fexp2(sc[mi][ni][1]);
                float p2 = fexp2(sc[mi][ni][2]);
                float p3 = fexp2(sc[mi][ni][3]);
                sc[mi][ni][0] = p0; sc[mi][ni][1] = p1;
                sc[mi][ni][2] = p2; sc[mi][ni][3] = p3;
                lrow[mi * 2 + 0] += p0 + p1;
                lrow[mi * 2 + 1] += p2 + p3;
            }

        // O += P V  (P packed in registers)
#pragma unroll
        for (int ksv = 0; ksv < 4; ksv++) {
            uint32_t pa[2][4];
#pragma unroll
            for (int mi = 0; mi < 2; mi++) {
                pa[mi][0] = packh(sc[mi][2 * ksv][0],     sc[mi][2 * ksv][1]);
                pa[mi][1] = packh(sc[mi][2 * ksv][2],     sc[mi][2 * ksv][3]);
                pa[mi][2] = packh(sc[mi][2 * ksv + 1][0], sc[mi][2 * ksv + 1][1]);
                pa[mi][3] = packh(sc[mi][2 * ksv + 1][2], sc[mi][2 * ksv + 1][3]);
            }
#pragma unroll
            for (int nip = 0; nip < 4; nip++) {
                uint32_t vf[4];
                ldsm4t(vf, vbuf + (uint32_t)((ksv * 16 + (g8 & 1) * 8 + l8) * 144
                                             + (nip * 16 + (g8 & 2) * 4) * 2));
                uint32_t v0[2] = {vf[0], vf[1]}, v1[2] = {vf[2], vf[3]};
                mma_f16(o[0][nip * 2],     pa[0], v0);
                mma_f16(o[0][nip * 2 + 1], pa[0], v1);
                mma_f16(o[1][nip * 2],     pa[1], v0);
                mma_f16(o[1][nip * 2 + 1], pa[1], v1);
            }
        }
        __syncthreads();   // tile consumed; buffer reusable for kt+2
    }

    // Single cross-lane l reduction (4 lanes of a quad share each row)
#pragma unroll
    for (int slot = 0; slot < 4; slot++) {
        lrow[slot] += __shfl_xor_sync(0xffffffffu, lrow[slot], 1);
        lrow[slot] += __shfl_xor_sync(0xffffffffu, lrow[slot], 2);
    }

    // Epilogue: fp16 out
#pragma unroll
    for (int slot = 0; slot < 4; slot++) {
        const int mi = slot >> 1, hh = slot & 1;
        const int row = m0 + mi * 16 + gid + hh * 8;
        const float inv = 1.f / lrow[slot];
        const size_t gb = ((size_t)b * Ss + q0 + row) * Dd + h * DHh;
#pragma unroll
        for (int ni = 0; ni < 8; ni++) {
            const int col = ni * 8 + tig * 2;
            *(uint32_t*)(atth + gb + col) =
                packh(o[mi][ni][hh * 2] * inv, o[mi][ni][hh * 2 + 1] * inv);
        }
    }
#undef ISSUE_KV
}

// ---------------------------------------------------------------------------
// LayerNorm over D=512, fp32 input: optional fp32 out + fp16 out
// ---------------------------------------------------------------------------
template <bool STORE32>
__global__ __launch_bounds__(128) void ln_kernel(
    const float* __restrict__ in, const float* __restrict__ g,
    const float* __restrict__ b, float* __restrict__ out, h16* __restrict__ oh)
{
    const int row = blockIdx.x;
    const int t   = threadIdx.x;

    float4 v = *(const float4*)(in + (size_t)row * Dd + t * 4);
    float s  = v.x + v.y + v.z + v.w;
    float ss = v.x * v.x + v.y * v.y + v.z * v.z + v.w * v.w;

#pragma unroll
    for (int off = 16; off > 0; off >>= 1) {
        s  += __shfl_xor_sync(0xffffffffu, s, off);
        ss += __shfl_xor_sync(0xffffffffu, ss, off);
    }
    __shared__ float sm_s[4], sm_ss[4];
    if ((t & 31) == 0) { sm_s[t >> 5] = s; sm_ss[t >> 5] = ss; }
    __syncthreads();
    s  = sm_s[0] + sm_s[1] + sm_s[2] + sm_s[3];
    ss = sm_ss[0] + sm_ss[1] + sm_ss[2] + sm_ss[3];

    const float inv_n = 1.f / (float)Dd;
    float mean = s * inv_n;
    float var  = ss * inv_n - mean * mean;
    float rstd = rsqrtf(var + 1e-5f);

    float4 g4 = *(const float4*)(g + t * 4);
    float4 b4 = *(const float4*)(b + t * 4);
    float4 rr;
    rr.x = (v.x - mean) * rstd * g4.x + b4.x;
    rr.y = (v.y - mean) * rstd * g4.y + b4.y;
    rr.z = (v.z - mean) * rstd * g4.z + b4.z;
    rr.w = (v.w - mean) * rstd * g4.w + b4.w;
    if (STORE32)
        *(float4*)(out + (size_t)row * Dd + t * 4) = rr;
    *(uint2*)(oh + (size_t)row * Dd + t * 4) =
        make_uint2(packh(rr.x, rr.y), packh(rr.z, rr.w));
}

// ---------------------------------------------------------------------------
// Launcher
// ---------------------------------------------------------------------------
extern "C" void kernel_launch(void* const* d_in, const int* in_sizes, int n_in,
                              void* d_out, int out_size)
{
    const float* X     = (const float*)d_in[0];
    const float* qkv_w = (const float*)d_in[1];
    const float* qkv_b = (const float*)d_in[2];
    const float* fc_w  = (const float*)d_in[3];
    const float* fc_b  = (const float*)d_in[4];
    const float* ln1_g = (const float*)d_in[5];
    const float* ln1_b = (const float*)d_in[6];
    const float* w1    = (const float*)d_in[7];
    const float* b1    = (const float*)d_in[8];
    const float* w2    = (const float*)d_in[9];
    const float* b2    = (const float*)d_in[10];
    const float* ln2_g = (const float*)d_in[11];
    const float* ln2_b = (const float*)d_in[12];
    float* out = (float*)d_out;

    float *x, *qkvbias;
    h16 *qkvb, *X16, *x16, *xn16, *at16, *h116;
    h16 *qkvT, *fcT, *w1T, *w2T;
    cudaGetSymbolAddress((void**)&x,    g_x);
    cudaGetSymbolAddress((void**)&qkvb, g_qkvb);
    cudaGetSymbolAddress((void**)&qkvbias, g_qkvbias);
    cudaGetSymbolAddress((void**)&X16,  g_X16);
    cudaGetSymbolAddress((void**)&x16,  g_x16);
    cudaGetSymbolAddress((void**)&xn16, g_xn16);
    cudaGetSymbolAddress((void**)&at16, g_at16);
    cudaGetSymbolAddress((void**)&h116, g_h116);
    cudaGetSymbolAddress((void**)&qkvT, g_qkvwT);
    cudaGetSymbolAddress((void**)&fcT,  g_fcwT);
    cudaGetSymbolAddress((void**)&w1T,  g_w1T);
    cudaGetSymbolAddress((void**)&w2T,  g_w2T);

    cudaFuncSetAttribute(attn_v2,
                         cudaFuncAttributeMaxDynamicSharedMemorySize, ATT2_SMEM);
    cudaFuncSetAttribute(gemm_mma<FLAG_OUTH, 128>,
                         cudaFuncAttributeMaxDynamicSharedMemorySize, GEMM_SMEM_128);
    cudaFuncSetAttribute(gemm_mma<FLAG_RELU | FLAG_OUTH, 128>,
                         cudaFuncAttributeMaxDynamicSharedMemorySize, GEMM_SMEM_128);
    cudaFuncSetAttribute(gemm_mma<FLAG_RES, 64>,
                         cudaFuncAttributeMaxDynamicSharedMemorySize, GEMM_SMEM_64);

    // One-time prep (4 launches)
    convert_h_kernel<<<(MTOT * Dd) / 1024, 256>>>(X, X16, MTOT * Dd);
    scale_bias_kernel<<<(NBLK * 1536 + 255) / 256, 256>>>(qkv_b, qkvbias);
    dim3 tb(32, 8);
    transpose_kernel<<<dim3(48, 16, NBLK), tb>>>(qkv_w, qkvT, 512, 1536, 1);
    transpose3_kernel<<<dim3(1280, 1, NBLK), tb>>>(fc_w, w1, w2, fcT, w1T, w2T);

    for (int blk = 0; blk < NBLK; blk++) {
        const float* xin   = (blk == 0) ? X   : x;    // fp32 residual input
        const h16*   xin16 = (blk == 0) ? X16 : x16;  // fp16 A input

        // qkv = x @ qkv_w(+scaled q) + bias -> fp16   [4096, 1536]
        gemm_mma<FLAG_OUTH, 128><<<dim3(12, 32), 256, GEMM_SMEM_128>>>(
            xin16, qkvT + (size_t)blk * 1536 * 512,
            qkvbias + (size_t)blk * 1536, nullptr, nullptr, qkvb, 512, 1536);

        // att = softmax(q k^T) v -> fp16  (2 CTAs/SM, proven)
        attn_v2<<<dim3(Ss / 128, Hh, Bb), 128, ATT2_SMEM>>>(qkvb, at16);

        // x = xin + att @ fc_w + fc_b   (MT=64: 256 CTAs, 2/SM)
        gemm_mma<FLAG_RES, 64><<<dim3(4, 64), 256, GEMM_SMEM_64>>>(
            at16, fcT + (size_t)blk * 512 * 512,
            fc_b + (size_t)blk * 512, xin, x, nullptr, 512, 512);

        // xn16 = ln1(x)  (fp16 only; x preserved as w2 residual)
        ln_kernel<false><<<MTOT, 128>>>(x, ln1_g + (size_t)blk * Dd,
                                        ln1_b + (size_t)blk * Dd, nullptr, xn16);

        // h1 = relu(xn @ w1 + b1) -> fp16
        gemm_mma<FLAG_RELU | FLAG_OUTH, 128><<<dim3(8, 32), 256, GEMM_SMEM_128>>>(
            xn16, w1T + (size_t)blk * 1024 * 512,
            b1 + (size_t)blk * 1024, nullptr, nullptr, h116, 512, 1024);

        // x = x + h1 @ w2 + b2   (MT=64)
        gemm_mma<FLAG_RES, 64><<<dim3(4, 64), 256, GEMM_SMEM_64>>>(
            h116, w2T + (size_t)blk * 512 * 1024,
            b2 + (size_t)blk * 512, x, x, nullptr, 1024, 512);

        // x = ln2(x)   (last block writes straight to d_out; fp16 to x16)
        ln_kernel<true><<<MTOT, 128>>>(x, ln2_g + (size_t)blk * Dd,
                                       ln2_b + (size_t)blk * Dd,
                                       (blk == NBLK - 1) ? out : x, x16);
    }
}